// round 10
// baseline (speedup 1.0000x reference)
#include <cuda_runtime.h>
#include <cuda_bf16.h>
#include <cuda_fp16.h>
#include <cstdint>

#define NN 50000
#define EE 800000
#define INDIM 256
#define HH 128
#define LLAYERS 4
#define CC 10
#define LN_EPS 1e-5f

// ---------------- scratch (device globals; no allocation) ----------------
__device__ int   d_indeg[2][NN];
__device__ int   d_rowptr[2][NN + 1];
__device__ int   d_cursor[2][NN];
__device__ float d_dinv[2][NN];
__device__ __align__(16) int2 d_edge[2][EE];      // {src, w_bits}
__device__ float d_x[2][(size_t)NN * HH];
__device__ __align__(16) __half d_h[2][(size_t)NN * HH];
__device__ int   d_blksum[2][64];

// pre-transposed, bf16-split weights: layout [n][k] (K-major rows of W^T)
__device__ __align__(16) __nv_bfloat16 d_wredT_h[2][HH * INDIM];
__device__ __align__(16) __nv_bfloat16 d_wredT_l[2][HH * INDIM];
__device__ __align__(16) __nv_bfloat16 d_wT_h[2][LLAYERS][HH * HH];
__device__ __align__(16) __nv_bfloat16 d_wT_l[2][LLAYERS][HH * HH];

// ---------------- PTX helpers ----------------
__device__ __forceinline__ uint32_t smem_u32(const void* p) {
    uint32_t a;
    asm("{ .reg .u64 t; cvta.to.shared.u64 t, %1; cvt.u32.u64 %0, t; }" : "=r"(a) : "l"(p));
    return a;
}

__device__ __forceinline__ void ldsm4(uint32_t* r, uint32_t addr) {
    asm volatile("ldmatrix.sync.aligned.m8n8.x4.shared.b16 {%0,%1,%2,%3}, [%4];"
                 : "=r"(r[0]), "=r"(r[1]), "=r"(r[2]), "=r"(r[3]) : "r"(addr));
}

__device__ __forceinline__ void mma16816(float* d, const uint32_t* a, const uint32_t* b) {
    asm volatile(
        "mma.sync.aligned.m16n8k16.row.col.f32.bf16.bf16.f32 "
        "{%0,%1,%2,%3}, {%4,%5,%6,%7}, {%8,%9}, {%0,%1,%2,%3};"
        : "+f"(d[0]), "+f"(d[1]), "+f"(d[2]), "+f"(d[3])
        : "r"(a[0]), "r"(a[1]), "r"(a[2]), "r"(a[3]), "r"(b[0]), "r"(b[1]));
}

#define CP_ASYNC16(dst, src) \
    asm volatile("cp.async.cg.shared.global [%0], [%1], 16;" :: "r"(dst), "l"(src))
#define CP_COMMIT() asm volatile("cp.async.commit_group;")
#define CP_WAIT0()  asm volatile("cp.async.wait_group 0;" ::: "memory")

// ---------------- CSR build (gridDim.y = 2 : both graph-streams per launch) ----
__global__ void k_zero() {
    int s = blockIdx.y;
    int i = blockIdx.x * blockDim.x + threadIdx.x;
    if (i < NN) d_indeg[s][i] = 0;
}

__global__ void k_hist(const int* __restrict__ dst0, const int* __restrict__ dst1) {
    int s = blockIdx.y;
    const int* dst = s ? dst1 : dst0;
    int e = blockIdx.x * blockDim.x + threadIdx.x;
    if (e < EE) atomicAdd(&d_indeg[s][dst[e]], 1);
}

__global__ void k_scan1() {
    __shared__ int sh[1024];
    int s = blockIdx.y;
    int b = blockIdx.x, t = threadIdx.x, i = b * 1024 + t;
    int v = (i < NN) ? d_indeg[s][i] : 0;
    sh[t] = v;
    __syncthreads();
    #pragma unroll
    for (int off = 1; off < 1024; off <<= 1) {
        int x = (t >= off) ? sh[t - off] : 0;
        __syncthreads();
        sh[t] += x;
        __syncthreads();
    }
    if (i < NN) {
        d_rowptr[s][i] = sh[t] - v;
        d_dinv[s][i]   = rsqrtf((float)(v + 1));
    }
    if (t == 1023) d_blksum[s][b] = sh[t];
}

__global__ void k_scan2() {
    __shared__ int sh[64];
    int s = blockIdx.y;
    int t = threadIdx.x;
    int v = (t < 49) ? d_blksum[s][t] : 0;
    sh[t] = v;
    __syncthreads();
    #pragma unroll
    for (int off = 1; off < 64; off <<= 1) {
        int x = (t >= off) ? sh[t - off] : 0;
        __syncthreads();
        sh[t] += x;
        __syncthreads();
    }
    if (t < 49) d_blksum[s][t] = sh[t] - v;
}

__global__ void k_scan3() {
    int s = blockIdx.y;
    int b = blockIdx.x, i = b * 1024 + threadIdx.x;
    if (i < NN) {
        int r = d_rowptr[s][i] + d_blksum[s][b];
        d_rowptr[s][i] = r;
        d_cursor[s][i] = r;
    }
    if (i == 0) d_rowptr[s][NN] = EE;
}

// fill packed edge records: {src, dinv[src]}
__global__ void k_fill(const int* __restrict__ src0, const int* __restrict__ dst0,
                       const int* __restrict__ src1, const int* __restrict__ dst1) {
    int s = blockIdx.y;
    const int* src = s ? src1 : src0;
    const int* dst = s ? dst1 : dst0;
    int e = blockIdx.x * blockDim.x + threadIdx.x;
    if (e < EE) {
        int u = src[e];
        int pos = atomicAdd(&d_cursor[s][dst[e]], 1);
        d_edge[s][pos] = make_int2(u, __float_as_int(d_dinv[s][u]));
    }
}

// ---------------- weight prep: transpose + bf16 hi/lo split ----------------
__global__ void k_prep(const float* __restrict__ Wred0, const float* __restrict__ Wred1,
                       const float* __restrict__ W0, const float* __restrict__ W1) {
    const int PER_STREAM = INDIM * HH + LLAYERS * HH * HH;
    int i = blockIdx.x * blockDim.x + threadIdx.x;
    if (i >= 2 * PER_STREAM) return;
    int s = i >= PER_STREAM;
    int j = i - s * PER_STREAM;
    float w;
    __nv_bfloat16 *ph, *pl;
    if (j < INDIM * HH) {
        int k = j >> 7, n = j & 127;
        w = (s ? Wred1 : Wred0)[k * HH + n];
        ph = &d_wredT_h[s][n * INDIM + k];
        pl = &d_wredT_l[s][n * INDIM + k];
    } else {
        int r = j - INDIM * HH;
        int l = r >> 14;
        int k = (r >> 7) & 127, n = r & 127;
        w = (s ? W1 : W0)[l * HH * HH + k * HH + n];
        ph = &d_wT_h[s][l][n * HH + k];
        pl = &d_wT_l[s][l][n * HH + k];
    }
    __nv_bfloat16 h = __float2bfloat16(w);
    *ph = h;
    *pl = __float2bfloat16(w - __bfloat162float(h));
}

// ---------------- mma.sync bf16 GEMM (3-pass compensated), batched over s ----
template <int KTOT, bool HOUT>
__global__ void __launch_bounds__(256) k_gemm_mma(
    const float* __restrict__ A0, const float* __restrict__ A1,
    const float* __restrict__ bias0, const float* __restrict__ bias1,
    int l, int M)
{
    constexpr int RS = 80;
    __shared__ __align__(16) char smem[4 * 128 * RS];
    const uint32_t AS_H = smem_u32(smem);
    const uint32_t AS_L = AS_H + 128 * RS;
    const uint32_t BS_H = AS_H + 2 * 128 * RS;
    const uint32_t BS_L = AS_H + 3 * 128 * RS;

    int s = blockIdx.y;
    const float* A = s ? A1 : A0;
    const float* bias = s ? bias1 : bias0;
    const __nv_bfloat16* Bh = (KTOT == INDIM) ? d_wredT_h[s] : d_wT_h[s][l];
    const __nv_bfloat16* Bl = (KTOT == INDIM) ? d_wredT_l[s] : d_wT_l[s][l];

    int tid = threadIdx.x, w = tid >> 5, lane = tid & 31;
    int row0 = blockIdx.x * 128;
    int wm = (w >> 1) * 32, wn = (w & 1) * 64;

    float acc[2][8][4];
    #pragma unroll
    for (int i = 0; i < 2; i++)
        #pragma unroll
        for (int j = 0; j < 8; j++)
            #pragma unroll
            for (int q = 0; q < 4; q++) acc[i][j][q] = 0.f;

    int lrow = tid >> 1, lhalf = tid & 1;
    bool avalid = (row0 + lrow) < M;
    const float* aptr = A + (size_t)(row0 + lrow) * KTOT + lhalf * 16;
    const __nv_bfloat16* bhp = Bh + (size_t)lrow * KTOT + lhalf * 16;
    const __nv_bfloat16* blp = Bl + (size_t)lrow * KTOT + lhalf * 16;
    uint32_t ash_st = AS_H + lrow * RS + lhalf * 32;
    uint32_t asl_st = AS_L + lrow * RS + lhalf * 32;
    uint32_t bsh_st = BS_H + lrow * RS + lhalf * 32;
    uint32_t bsl_st = BS_L + lrow * RS + lhalf * 32;

    int a_r = lane & 15, a_k = (lane >> 4) * 8;
    int b_r = ((lane >> 4) << 3) + (lane & 7), b_k = ((lane >> 3) & 1) * 8;

    for (int c0 = 0; c0 < KTOT; c0 += 32) {
        CP_ASYNC16(bsh_st,      bhp);
        CP_ASYNC16(bsh_st + 16, bhp + 8);
        CP_ASYNC16(bsl_st,      blp);
        CP_ASYNC16(bsl_st + 16, blp + 8);
        CP_COMMIT();
        bhp += 32; blp += 32;

        float xv[16];
        if (avalid) {
            #pragma unroll
            for (int g = 0; g < 4; g++) {
                float4 v = *(const float4*)(aptr + g * 4);
                xv[g * 4] = v.x; xv[g * 4 + 1] = v.y; xv[g * 4 + 2] = v.z; xv[g * 4 + 3] = v.w;
            }
        } else {
            #pragma unroll
            for (int j = 0; j < 16; j++) xv[j] = 0.f;
        }
        aptr += 32;
        union { uint4 q[2]; __nv_bfloat16 b[16]; } hi, lo;
        #pragma unroll
        for (int j = 0; j < 16; j++) {
            __nv_bfloat16 h = __float2bfloat16(xv[j]);
            hi.b[j] = h;
            lo.b[j] = __float2bfloat16(xv[j] - __bfloat162float(h));
        }
        asm volatile("st.shared.v4.b32 [%0], {%1,%2,%3,%4};" :: "r"(ash_st),
            "r"(hi.q[0].x), "r"(hi.q[0].y), "r"(hi.q[0].z), "r"(hi.q[0].w));
        asm volatile("st.shared.v4.b32 [%0], {%1,%2,%3,%4};" :: "r"(ash_st + 16),
            "r"(hi.q[1].x), "r"(hi.q[1].y), "r"(hi.q[1].z), "r"(hi.q[1].w));
        asm volatile("st.shared.v4.b32 [%0], {%1,%2,%3,%4};" :: "r"(asl_st),
            "r"(lo.q[0].x), "r"(lo.q[0].y), "r"(lo.q[0].z), "r"(lo.q[0].w));
        asm volatile("st.shared.v4.b32 [%0], {%1,%2,%3,%4};" :: "r"(asl_st + 16),
            "r"(lo.q[1].x), "r"(lo.q[1].y), "r"(lo.q[1].z), "r"(lo.q[1].w));

        CP_WAIT0();
        __syncthreads();

        #pragma unroll
        for (int ks = 0; ks < 2; ks++) {
            int kb = ks * 16;
            uint32_t ah[2][4], al[2][4];
            #pragma unroll
            for (int mt = 0; mt < 2; mt++) {
                uint32_t off = (uint32_t)((wm + mt * 16 + a_r) * RS + (kb + a_k) * 2);
                ldsm4(ah[mt], AS_H + off);
                ldsm4(al[mt], AS_L + off);
            }
            uint32_t bh[4][4], bl[4][4];
            #pragma unroll
            for (int nt = 0; nt < 4; nt++) {
                uint32_t off = (uint32_t)((wn + nt * 16 + b_r) * RS + (kb + b_k) * 2);
                ldsm4(bh[nt], BS_H + off);
                ldsm4(bl[nt], BS_L + off);
            }
            #pragma unroll
            for (int mt = 0; mt < 2; mt++) {
                #pragma unroll
                for (int j = 0; j < 8; j++) {
                    const uint32_t* ph = &bh[j >> 1][(j & 1) * 2];
                    const uint32_t* pl = &bl[j >> 1][(j & 1) * 2];
                    mma16816(acc[mt][j], ah[mt], ph);
                    mma16816(acc[mt][j], ah[mt], pl);
                    mma16816(acc[mt][j], al[mt], ph);
                }
            }
        }
        __syncthreads();
    }

    int qr = lane >> 2, qc = (lane & 3) * 2;
    #pragma unroll
    for (int mt = 0; mt < 2; mt++) {
        int r0g = row0 + wm + mt * 16 + qr;
        #pragma unroll
        for (int j = 0; j < 8; j++) {
            int col = wn + j * 8 + qc;
            float b0 = 0.f, b1 = 0.f;
            if (bias) { b0 = bias[col]; b1 = bias[col + 1]; }
            if (HOUT) {
                __half* Ch = d_h[s];
                if (r0g < M)
                    *(__half2*)(Ch + (size_t)r0g * HH + col) =
                        __floats2half2_rn(acc[mt][j][0] + b0, acc[mt][j][1] + b1);
                if (r0g + 8 < M)
                    *(__half2*)(Ch + (size_t)(r0g + 8) * HH + col) =
                        __floats2half2_rn(acc[mt][j][2] + b0, acc[mt][j][3] + b1);
            } else {
                float* Cf = d_x[s];
                if (r0g < M)
                    *(float2*)(Cf + (size_t)r0g * HH + col) =
                        make_float2(acc[mt][j][0] + b0, acc[mt][j][1] + b1);
                if (r0g + 8 < M)
                    *(float2*)(Cf + (size_t)(r0g + 8) * HH + col) =
                        make_float2(acc[mt][j][2] + b0, acc[mt][j][3] + b1);
            }
        }
    }
}

// ---------------- fused GCN aggregate + bias + LayerNorm + ReLU + residual ----------------
// warp per node; split-warp gather: each half-warp owns one edge, lane q = lane&15
// loads uint4 (8 fp16 channels: 8q..8q+7). Merge halves via shfl_down(16).
__device__ __forceinline__ void acc8(float* acc, uint4 v, float w) {
    __half2* hp = (__half2*)&v;
    #pragma unroll
    for (int j = 0; j < 4; j++) {
        float2 f = __half22float2(hp[j]);
        acc[2 * j]     += w * f.x;
        acc[2 * j + 1] += w * f.y;
    }
}

__global__ void __launch_bounds__(256) k_agg(
    const float* __restrict__ b0p, const float* __restrict__ b1p,
    const float* __restrict__ g0p, const float* __restrict__ g1p,
    const float* __restrict__ e0p, const float* __restrict__ e1p,
    int l)
{
    int s = blockIdx.y;
    int v = (blockIdx.x * blockDim.x + threadIdx.x) >> 5;
    int lane = threadIdx.x & 31;
    if (v >= NN) return;
    int half = lane >> 4, q = lane & 15;

    const float* bias  = (s ? b1p : b0p) + l * HH;
    const float* gamma = (s ? g1p : g0p) + l * HH;
    const float* beta  = (s ? e1p : e0p) + l * HH;
    const __half* hb = d_h[s];
    const int2* edges = d_edge[s];
    float* x = d_x[s];

    float acc0[8], acc1[8];
    #pragma unroll
    for (int j = 0; j < 8; j++) { acc0[j] = 0.f; acc1[j] = 0.f; }

    int beg = d_rowptr[s][v], end = d_rowptr[s][v + 1];
    float dv = d_dinv[s][v];

    int i = beg;
    for (; i + 4 <= end; i += 4) {
        int2 eA = edges[i + half];
        int2 eB = edges[i + 2 + half];
        uint4 vA = *(const uint4*)(hb + (size_t)eA.x * HH + q * 8);
        uint4 vB = *(const uint4*)(hb + (size_t)eB.x * HH + q * 8);
        acc8(acc0, vA, __int_as_float(eA.y));
        acc8(acc1, vB, __int_as_float(eB.y));
    }
    if (i + 2 <= end) {
        int2 e = edges[i + half];
        uint4 ve = *(const uint4*)(hb + (size_t)e.x * HH + q * 8);
        acc8(acc0, ve, __int_as_float(e.y));
        i += 2;
    }
    if (i < end && half == 0) {                 // odd tail edge -> half 0
        int2 e = edges[i];
        uint4 ve = *(const uint4*)(hb + (size_t)e.x * HH + q * 8);
        acc8(acc0, ve, __int_as_float(e.y));
    }
    if (half == 1) {                            // self loop -> half 1
        uint4 ve = *(const uint4*)(hb + (size_t)v * HH + q * 8);
        acc8(acc1, ve, dv);
    }

    // merge the two unroll sets and the two half-warps
    float a[8];
    #pragma unroll
    for (int j = 0; j < 8; j++) {
        float t = acc0[j] + acc1[j];
        t += __shfl_down_sync(0xFFFFFFFFu, t, 16);
        a[j] = t;                               // valid on lanes 0..15
    }

    int ch = q * 8;
    float4 bA, bB, gA, gB, eA2, eB2;
    if (half == 0) {
        bA = *(const float4*)(bias + ch);  bB = *(const float4*)(bias + ch + 4);
        gA = *(const float4*)(gamma + ch); gB = *(const float4*)(gamma + ch + 4);
        eA2 = *(const float4*)(beta + ch); eB2 = *(const float4*)(beta + ch + 4);
        a[0] = a[0] * dv + bA.x; a[1] = a[1] * dv + bA.y;
        a[2] = a[2] * dv + bA.z; a[3] = a[3] * dv + bA.w;
        a[4] = a[4] * dv + bB.x; a[5] = a[5] * dv + bB.y;
        a[6] = a[6] * dv + bB.z; a[7] = a[7] * dv + bB.w;
    }

    float sum = 0.f;
    if (half == 0) {
        #pragma unroll
        for (int j = 0; j < 8; j++) sum += a[j];
    }
    #pragma unroll
    for (int o = 16; o; o >>= 1) sum += __shfl_xor_sync(0xFFFFFFFFu, sum, o);
    float mu = sum * (1.f / HH);

    float var = 0.f;
    if (half == 0) {
        #pragma unroll
        for (int j = 0; j < 8; j++) { float d = a[j] - mu; var += d * d; }
    }
    #pragma unroll
    for (int o = 16; o; o >>= 1) var += __shfl_xor_sync(0xFFFFFFFFu, var, o);
    float rstd = rsqrtf(var * (1.f / HH) + LN_EPS);

    if (half == 0) {
        float* xp = x + (size_t)v * HH + ch;
        float4 r0 = *(float4*)xp;
        float4 r1 = *(float4*)(xp + 4);
        r0.x += fmaxf((a[0] - mu) * rstd * gA.x + eA2.x, 0.f);
        r0.y += fmaxf((a[1] - mu) * rstd * gA.y + eA2.y, 0.f);
        r0.z += fmaxf((a[2] - mu) * rstd * gA.z + eA2.z, 0.f);
        r0.w += fmaxf((a[3] - mu) * rstd * gA.w + eA2.w, 0.f);
        r1.x += fmaxf((a[4] - mu) * rstd * gB.x + eB2.x, 0.f);
        r1.y += fmaxf((a[5] - mu) * rstd * gB.y + eB2.y, 0.f);
        r1.z += fmaxf((a[6] - mu) * rstd * gB.z + eB2.z, 0.f);
        r1.w += fmaxf((a[7] - mu) * rstd * gB.w + eB2.w, 0.f);
        *(float4*)xp = r0;
        *(float4*)(xp + 4) = r1;
    }
}

// ---------------- classifier ----------------
__global__ void __launch_bounds__(256) k_cls(const float* __restrict__ Wcls,
                                             const float* __restrict__ bcls,
                                             float* __restrict__ out) {
    __shared__ float WsT[CC * 2 * HH];
    __shared__ float bs[CC];
    for (int i = threadIdx.x; i < 2 * HH * CC; i += blockDim.x) {
        int k = i / CC, c = i % CC;
        WsT[c * (2 * HH) + k] = Wcls[i];
    }
    if (threadIdx.x < CC) bs[threadIdx.x] = bcls[threadIdx.x];
    __syncthreads();

    int v = (blockIdx.x * blockDim.x + threadIdx.x) >> 5;
    int lane = threadIdx.x & 31;
    if (v >= NN) return;

    float acc[CC];
    #pragma unroll
    for (int c = 0; c < CC; c++) acc[c] = 0.f;

    const float* a = d_x[0] + (size_t)v * HH;
    const float* b = d_x[1] + (size_t)v * HH;
    #pragma unroll
    for (int kk = 0; kk < 4; kk++) {
        int k = lane + 32 * kk;
        float av = a[k];
        float bv = b[k];
        #pragma unroll
        for (int c = 0; c < CC; c++) {
            acc[c] += av * WsT[c * (2 * HH) + k];
            acc[c] += bv * WsT[c * (2 * HH) + 128 + k];
        }
    }
    #pragma unroll
    for (int c = 0; c < CC; c++)
        #pragma unroll
        for (int o = 16; o; o >>= 1) acc[c] += __shfl_xor_sync(0xFFFFFFFFu, acc[c], o);

    if (lane == 0) {
        float* op = out + (size_t)v * CC;
        #pragma unroll
        for (int c = 0; c < CC; c++) op[c] = acc[c] + bs[c];
    }
}

// ---------------- driver (single default stream — graph-capture safe) ----------------
extern "C" void kernel_launch(void* const* d_in, const int* in_sizes, int n_in,
                              void* d_out, int out_size) {
    const float* x_in[2]  = { (const float*)d_in[0], (const float*)d_in[1] };
    const float* Wred[2]  = { (const float*)d_in[2], (const float*)d_in[4] };
    const float* bred[2]  = { (const float*)d_in[3], (const float*)d_in[5] };
    const float* W[2]     = { (const float*)d_in[6],  (const float*)d_in[10] };
    const float* b[2]     = { (const float*)d_in[7],  (const float*)d_in[11] };
    const float* g[2]     = { (const float*)d_in[8],  (const float*)d_in[12] };
    const float* be[2]    = { (const float*)d_in[9],  (const float*)d_in[13] };
    const float* Wcls     = (const float*)d_in[14];
    const float* bcls     = (const float*)d_in[15];
    const int*   ei[2]    = { (const int*)d_in[16], (const int*)d_in[17] };
    float* out = (float*)d_out;

    void* p0;
    cudaGetSymbolAddress(&p0, d_x);
    float* px = (float*)p0;

    const int THR = 256;
    const dim3 gN((NN + THR - 1) / THR, 2);
    const dim3 gE((EE + THR - 1) / THR, 2);
    const dim3 gW((NN * 32 + THR - 1) / THR, 2);
    const dim3 gG((NN + 127) / 128, 2);
    const dim3 gS((NN + 1023) / 1024, 2);
    const dim3 gS2(1, 2);
    const int blkWarp1 = (NN * 32 + THR - 1) / THR;

    {
        const int TOT = 2 * (INDIM * HH + LLAYERS * HH * HH);
        k_prep<<<(TOT + THR - 1) / THR, THR>>>(Wred[0], Wred[1], W[0], W[1]);
    }

    // CSR build (both streams per launch)
    k_zero<<<gN, THR>>>();
    k_hist<<<gE, THR>>>(ei[0] + EE, ei[1] + EE);
    k_scan1<<<gS, 1024>>>();
    k_scan2<<<gS2, 64>>>();
    k_scan3<<<gS, 1024>>>();
    k_fill<<<gE, THR>>>(ei[0], ei[0] + EE, ei[1], ei[1] + EE);

    // dim-reduction GEMM (both streams)
    k_gemm_mma<INDIM, false><<<gG, 256>>>(x_in[0], x_in[1], bred[0], bred[1], 0, NN);

    // 4 layers (both streams per launch)
    for (int l = 0; l < LLAYERS; l++) {
        k_gemm_mma<HH, true><<<gG, 256>>>(px, px + (size_t)NN * HH, nullptr, nullptr, l, NN);
        k_agg<<<gW, THR>>>(b[0], b[1], g[0], g[1], be[0], be[1], l);
    }

    k_cls<<<blkWarp1, THR>>>(Wcls, bcls, out);
}